// round 11
// baseline (speedup 1.0000x reference)
#include <cuda_runtime.h>

#define N_BATCH 8
#define C 256
#define HW 1024
#define CPG 32
#define NH 32
#define D 8
#define THREE_C 768
#define TP 512   // t-pairs per head

typedef unsigned long long ull;

// Scratch (static __device__ arrays: allocation-free per harness rules)
__device__ float g_xn[N_BATCH * C * HW];        // 8 MB
__device__ float g_qkv[N_BATCH * THREE_C * HW]; // 24 MB
__device__ float g_y[N_BATCH * C * HW];         // 8 MB

// ---------------- f32x2 packed helpers (FFMA2 — PTX-only on sm_103a) -------
__device__ __forceinline__ ull pack2(float lo, float hi) {
    ull r;
    asm("mov.b64 %0, {%1, %2};" : "=l"(r) : "f"(lo), "f"(hi));
    return r;
}
__device__ __forceinline__ void unpack2(ull v, float& lo, float& hi) {
    asm("mov.b64 {%0, %1}, %2;" : "=f"(lo), "=f"(hi) : "l"(v));
}
__device__ __forceinline__ ull fma2(ull a, ull b, ull c) {
    ull d;
    asm("fma.rn.f32x2 %0, %1, %2, %3;" : "=l"(d) : "l"(a), "l"(b), "l"(c));
    return d;
}
__device__ __forceinline__ ull mul2(ull a, ull b) {
    ull d;
    asm("mul.rn.f32x2 %0, %1, %2;" : "=l"(d) : "l"(a), "l"(b));
    return d;
}
__device__ __forceinline__ ull add2(ull a, ull b) {
    ull d;
    asm("add.rn.f32x2 %0, %1, %2;" : "=l"(d) : "l"(a), "l"(b));
    return d;
}
__device__ __forceinline__ float ex2f(float x) {
    float r;
    asm("ex2.approx.f32 %0, %1;" : "=f"(r) : "f"(x));
    return r;
}

// ---------------------------------------------------------------------------
// Kernel 1: GroupNorm (8 groups of 32 channels x 1024). One block per (n,g).
// ---------------------------------------------------------------------------
__global__ void gn_kernel(const float* __restrict__ x,
                          const float* __restrict__ gn_w,
                          const float* __restrict__ gn_b) {
    int n = blockIdx.x >> 3;
    int g = blockIdx.x & 7;
    const float4* xp = (const float4*)(x + (size_t)(n * C + g * CPG) * HW);
    float4* op = (float4*)(g_xn + (size_t)(n * C + g * CPG) * HW);

    float s = 0.f, ss = 0.f;
#pragma unroll 4
    for (int i = threadIdx.x; i < 8192; i += 256) {
        float4 v = xp[i];
        s  += v.x + v.y + v.z + v.w;
        ss += v.x * v.x + v.y * v.y + v.z * v.z + v.w * v.w;
    }
#pragma unroll
    for (int off = 16; off; off >>= 1) {
        s  += __shfl_down_sync(0xffffffffu, s, off);
        ss += __shfl_down_sync(0xffffffffu, ss, off);
    }
    __shared__ float rs[8], rss[8];
    __shared__ float s_mu, s_rinv;
    int warp = threadIdx.x >> 5, lane = threadIdx.x & 31;
    if (lane == 0) { rs[warp] = s; rss[warp] = ss; }
    __syncthreads();
    if (threadIdx.x == 0) {
        float ts = 0.f, tss = 0.f;
#pragma unroll
        for (int w = 0; w < 8; ++w) { ts += rs[w]; tss += rss[w]; }
        float mu  = ts * (1.f / 32768.f);
        float var = tss * (1.f / 32768.f) - mu * mu;
        s_mu = mu;
        s_rinv = rsqrtf(var + 1e-5f);
    }
    __syncthreads();
    float mu = s_mu, rinv = s_rinv;
#pragma unroll 4
    for (int i = threadIdx.x; i < 8192; i += 256) {
        int cl = i >> 8;  // 256 float4 per channel
        float w = __ldg(&gn_w[g * CPG + cl]) * rinv;
        float b = __ldg(&gn_b[g * CPG + cl]) - mu * w;
        float4 v = xp[i];
        float4 o;
        o.x = v.x * w + b; o.y = v.y * w + b;
        o.z = v.z * w + b; o.w = v.w * w + b;
        op[i] = o;
    }
}

// ---------------------------------------------------------------------------
// Kernel 2/4: batched GEMM  Out[n][o][t] = sum_c W[o][c]*In[n][c][t] + bias[o]
// (+ optional residual X). K = 256. Tile 64x64, BK=32, 4x4/thread.
// Double-buffered register-staged prefetch (proven R7 skeleton) + f32x2 MACs:
// accumulators packed over adjacent m (same 16 regs as scalar), A-pairs come
// free as ulonglong2 from the m-contiguous As layout, B broadcasts packed on
// the idle ALU pipe. FMA-pipe cycles per k: 32 -> 16.
// ---------------------------------------------------------------------------
template <bool RESIDUAL>
__global__ void gemm_kernel(const float* __restrict__ W,
                            const float* __restrict__ bias,
                            const float* __restrict__ In,
                            const float* __restrict__ X,
                            float* __restrict__ Out, int M) {
    __shared__ __align__(16) float As[2][32][68];  // [buf][c][o]
    __shared__ __align__(16) float Bs[2][32][64];  // [buf][c][t]

    int n  = blockIdx.z;
    int mo = blockIdx.y * 64;
    int to = blockIdx.x * 64;
    int tid = threadIdx.x;
    int tm = tid >> 4, tn = tid & 15;

    const float* Wp = W + (size_t)mo * C;
    const float* Ip = In + (size_t)n * (C * HW) + to;

    int ao0 = tid >> 3,          ac0 = (tid & 7) * 4;
    int ao1 = (tid + 256) >> 3,  ac1 = (tid & 7) * 4;
    int bc0 = tid >> 4,  bt0 = (tid & 15) * 4;
    int bc1 = bc0 + 16;

    const float* ApA = Wp + ao0 * C + ac0;
    const float* ApB = Wp + ao1 * C + ac1;
    const float* BpA = Ip + bc0 * HW + bt0;
    const float* BpB = Ip + bc1 * HW + bt0;

    float4 a0r = *(const float4*)(ApA);
    float4 a1r = *(const float4*)(ApB);
    float4 b0r = *(const float4*)(BpA);
    float4 b1r = *(const float4*)(BpB);

    ull acc2[2][4];  // packed over (m, m+1) pairs; same footprint as scalar 4x4
#pragma unroll
    for (int i = 0; i < 2; ++i)
#pragma unroll
        for (int j = 0; j < 4; ++j) acc2[i][j] = 0ull;

    As[0][ac0 + 0][ao0] = a0r.x; As[0][ac0 + 1][ao0] = a0r.y;
    As[0][ac0 + 2][ao0] = a0r.z; As[0][ac0 + 3][ao0] = a0r.w;
    As[0][ac1 + 0][ao1] = a1r.x; As[0][ac1 + 1][ao1] = a1r.y;
    As[0][ac1 + 2][ao1] = a1r.z; As[0][ac1 + 3][ao1] = a1r.w;
    *(float4*)&Bs[0][bc0][bt0] = b0r;
    *(float4*)&Bs[0][bc1][bt0] = b1r;
    __syncthreads();

    int buf = 0;
#pragma unroll 1
    for (int k0 = 32; ; k0 += 32) {
        bool more = (k0 < C);
        if (more) {
            a0r = *(const float4*)(ApA + k0);
            a1r = *(const float4*)(ApB + k0);
            b0r = *(const float4*)(BpA + k0 * HW);
            b1r = *(const float4*)(BpB + k0 * HW);
        }
#pragma unroll
        for (int k = 0; k < 32; ++k) {
            ulonglong2 a = *(const ulonglong2*)&As[buf][k][tm * 4];
            float4 b = *(const float4*)&Bs[buf][k][tn * 4];
            ull b0 = pack2(b.x, b.x), b1 = pack2(b.y, b.y);
            ull b2 = pack2(b.z, b.z), b3 = pack2(b.w, b.w);
            acc2[0][0] = fma2(a.x, b0, acc2[0][0]);
            acc2[0][1] = fma2(a.x, b1, acc2[0][1]);
            acc2[0][2] = fma2(a.x, b2, acc2[0][2]);
            acc2[0][3] = fma2(a.x, b3, acc2[0][3]);
            acc2[1][0] = fma2(a.y, b0, acc2[1][0]);
            acc2[1][1] = fma2(a.y, b1, acc2[1][1]);
            acc2[1][2] = fma2(a.y, b2, acc2[1][2]);
            acc2[1][3] = fma2(a.y, b3, acc2[1][3]);
        }
        if (!more) break;
        __syncthreads();
        int nb = buf ^ 1;
        As[nb][ac0 + 0][ao0] = a0r.x; As[nb][ac0 + 1][ao0] = a0r.y;
        As[nb][ac0 + 2][ao0] = a0r.z; As[nb][ac0 + 3][ao0] = a0r.w;
        As[nb][ac1 + 0][ao1] = a1r.x; As[nb][ac1 + 1][ao1] = a1r.y;
        As[nb][ac1 + 2][ao1] = a1r.z; As[nb][ac1 + 3][ao1] = a1r.w;
        *(float4*)&Bs[nb][bc0][bt0] = b0r;
        *(float4*)&Bs[nb][bc1][bt0] = b1r;
        buf = nb;
        __syncthreads();
    }

#pragma unroll
    for (int mp = 0; mp < 2; ++mp) {
        float lo[4], hi[4];
#pragma unroll
        for (int j = 0; j < 4; ++j) unpack2(acc2[mp][j], lo[j], hi[j]);
#pragma unroll
        for (int half = 0; half < 2; ++half) {
            float* rr = half ? hi : lo;
            int o = mo + tm * 4 + mp * 2 + half;
            float bi = __ldg(&bias[o]);
            size_t off = (size_t)(n * M + o) * HW + to + tn * 4;
            float4 r;
            r.x = rr[0] + bi; r.y = rr[1] + bi;
            r.z = rr[2] + bi; r.w = rr[3] + bi;
            if (RESIDUAL) {
                float4 xv = *(const float4*)(X + off);
                r.x += xv.x; r.y += xv.y; r.z += xv.z; r.w += xv.w;
            }
            *(float4*)(Out + off) = r;
        }
    }
}

// ---------------------------------------------------------------------------
// Kernel 3: attention with t-parity packing. Block = (h, n, s-half); 256
// threads x 2 s-rows each. SMEM holds FULL K,V (64 KB) as natural even/odd
// t-pairs: kS[tp][2d..2d+1] = {k[2tp][d], k[2tp+1][d]} — straight float2
// copies from gmem, NO duplication, so the mainloop does 8 LDS.128 per tp
// shared across 2 rows (half the crossbar traffic of the dup layout).
// Streams are packed over t-parity; one horizontal add at the end.
// No max subtraction (scores ~N(0,1)); exp2 via pre-scaled q.
// ---------------------------------------------------------------------------
__global__ void __launch_bounds__(256, 2) attn_kernel() {
    extern __shared__ float sm[];
    float* kS = sm;              // [tp][16]
    float* vS = sm + TP * 16;

    int h = blockIdx.x, n = blockIdx.y, sh = blockIdx.z;
    const float* base = g_qkv + (size_t)n * (THREE_C * HW);
    const float* qg = base + (h * D) * HW;
    const float* kg = base + (C + h * D) * HW;
    const float* vg = base + (2 * C + h * D) * HW;

    // Fill: float2 gmem loads are exactly the (even,odd) pairs we need.
    for (int tp = threadIdx.x; tp < TP; tp += 256) {
        float* kd = kS + tp * 16;
        float* vd = vS + tp * 16;
#pragma unroll
        for (int d = 0; d < 8; ++d) {
            *(float2*)(kd + 2 * d) = *(const float2*)(kg + d * HW + 2 * tp);
            *(float2*)(vd + 2 * d) = *(const float2*)(vg + d * HW + 2 * tp);
        }
    }
    __syncthreads();

    // q pre-scaled by (1/sqrt(8)) * log2(e); duplicated into both lanes.
    const float qscale = 0.35355339059327373f * 1.4426950408889634f;
    int s0 = sh * 512 + threadIdx.x;   // row A
    int s1 = s0 + 256;                 // row B
    ull qa[8], qb[8];
#pragma unroll
    for (int d = 0; d < 8; ++d) {
        const float* qd = qg + d * HW;
        float q0 = qd[s0] * qscale, q1 = qd[s1] * qscale;
        qa[d] = pack2(q0, q0);
        qb[d] = pack2(q1, q1);
    }

    ull acca[8], accb[8];
#pragma unroll
    for (int d = 0; d < 8; ++d) { acca[d] = 0ull; accb[d] = 0ull; }
    ull la = 0ull, lb = 0ull;

#pragma unroll 1
    for (int tp = 0; tp < TP; ++tp) {
        const ulonglong2* kp = (const ulonglong2*)(kS + tp * 16);
        ulonglong2 k01 = kp[0], k23 = kp[1], k45 = kp[2], k67 = kp[3];
        ull sa = mul2(qa[0], k01.x);
        ull sb = mul2(qb[0], k01.x);
        sa = fma2(qa[1], k01.y, sa); sb = fma2(qb[1], k01.y, sb);
        sa = fma2(qa[2], k23.x, sa); sb = fma2(qb[2], k23.x, sb);
        sa = fma2(qa[3], k23.y, sa); sb = fma2(qb[3], k23.y, sb);
        sa = fma2(qa[4], k45.x, sa); sb = fma2(qb[4], k45.x, sb);
        sa = fma2(qa[5], k45.y, sa); sb = fma2(qb[5], k45.y, sb);
        sa = fma2(qa[6], k67.x, sa); sb = fma2(qb[6], k67.x, sb);
        sa = fma2(qa[7], k67.y, sa); sb = fma2(qb[7], k67.y, sb);

        float f0, f1, f2, f3;
        unpack2(sa, f0, f1);
        unpack2(sb, f2, f3);
        ull ea = pack2(ex2f(f0), ex2f(f1));   // weights for (t_even, t_odd)
        ull eb = pack2(ex2f(f2), ex2f(f3));
        la = add2(la, ea);
        lb = add2(lb, eb);

        const ulonglong2* vp = (const ulonglong2*)(vS + tp * 16);
        ulonglong2 v01 = vp[0], v23 = vp[1], v45 = vp[2], v67 = vp[3];
        acca[0] = fma2(ea, v01.x, acca[0]); accb[0] = fma2(eb, v01.x, accb[0]);
        acca[1] = fma2(ea, v01.y, acca[1]); accb[1] = fma2(eb, v01.y, accb[1]);
        acca[2] = fma2(ea, v23.x, acca[2]); accb[2] = fma2(eb, v23.x, accb[2]);
        acca[3] = fma2(ea, v23.y, acca[3]); accb[3] = fma2(eb, v23.y, accb[3]);
        acca[4] = fma2(ea, v45.x, acca[4]); accb[4] = fma2(eb, v45.x, accb[4]);
        acca[5] = fma2(ea, v45.y, acca[5]); accb[5] = fma2(eb, v45.y, accb[5]);
        acca[6] = fma2(ea, v67.x, acca[6]); accb[6] = fma2(eb, v67.x, accb[6]);
        acca[7] = fma2(ea, v67.y, acca[7]); accb[7] = fma2(eb, v67.y, accb[7]);
    }

    // Horizontal reduce the t-parity lanes, normalize, store.
    float la0, la1, lb0, lb1;
    unpack2(la, la0, la1);
    unpack2(lb, lb0, lb1);
    float invA = 1.f / (la0 + la1);
    float invB = 1.f / (lb0 + lb1);
    float* ypA = g_y + (size_t)(n * C + h * D) * HW + s0;
    float* ypB = g_y + (size_t)(n * C + h * D) * HW + s1;
#pragma unroll
    for (int d = 0; d < 8; ++d) {
        float a0, a1, b0, b1;
        unpack2(acca[d], a0, a1);
        unpack2(accb[d], b0, b1);
        ypA[d * HW] = (a0 + a1) * invA;
        ypB[d * HW] = (b0 + b1) * invB;
    }
}

// ---------------------------------------------------------------------------
extern "C" void kernel_launch(void* const* d_in, const int* in_sizes, int n_in,
                              void* d_out, int out_size) {
    const float* x     = (const float*)d_in[0];
    const float* gn_w  = (const float*)d_in[1];
    const float* gn_b  = (const float*)d_in[2];
    const float* qkv_w = (const float*)d_in[3];
    const float* qkv_b = (const float*)d_in[4];
    const float* out_w = (const float*)d_in[5];
    const float* out_b = (const float*)d_in[6];
    float* out = (float*)d_out;

    float *p_xn, *p_qkv, *p_y;
    cudaGetSymbolAddress((void**)&p_xn, g_xn);
    cudaGetSymbolAddress((void**)&p_qkv, g_qkv);
    cudaGetSymbolAddress((void**)&p_y, g_y);

    // 1. GroupNorm -> g_xn
    gn_kernel<<<64, 256>>>(x, gn_w, gn_b);

    // 2. QKV GEMM: g_qkv[n][768][1024]
    gemm_kernel<false><<<dim3(16, 12, 8), 256>>>(
        qkv_w, qkv_b, p_xn, nullptr, p_qkv, THREE_C);

    // 3. Attention -> g_y  (64 KB dynamic SMEM: full K+V as t-parity pairs)
    const int attn_smem = 2 * TP * 16 * sizeof(float);  // 65536
    cudaFuncSetAttribute(attn_kernel,
                         cudaFuncAttributeMaxDynamicSharedMemorySize, attn_smem);
    attn_kernel<<<dim3(NH, N_BATCH, 2), 256, attn_smem>>>();

    // 4. Output projection + residual -> d_out
    gemm_kernel<true><<<dim3(16, 4, 8), 256>>>(
        out_w, out_b, p_y, x, out, C);
}

// round 16
// speedup vs baseline: 1.0879x; 1.0879x over previous
#include <cuda_runtime.h>

#define N_BATCH 8
#define C 256
#define HW 1024
#define CPG 32
#define NH 32
#define D 8
#define THREE_C 768
#define TP 512   // t-pairs per head

typedef unsigned long long ull;

// Scratch (static __device__ arrays: allocation-free per harness rules)
__device__ float g_xn[N_BATCH * C * HW];        // 8 MB
__device__ float g_qkv[N_BATCH * THREE_C * HW]; // 24 MB
__device__ float g_y[N_BATCH * C * HW];         // 8 MB

// ---------------- f32x2 packed helpers (FFMA2 — PTX-only on sm_103a) -------
__device__ __forceinline__ ull pack2(float lo, float hi) {
    ull r;
    asm("mov.b64 %0, {%1, %2};" : "=l"(r) : "f"(lo), "f"(hi));
    return r;
}
__device__ __forceinline__ void unpack2(ull v, float& lo, float& hi) {
    asm("mov.b64 {%0, %1}, %2;" : "=f"(lo), "=f"(hi) : "l"(v));
}
__device__ __forceinline__ ull fma2(ull a, ull b, ull c) {
    ull d;
    asm("fma.rn.f32x2 %0, %1, %2, %3;" : "=l"(d) : "l"(a), "l"(b), "l"(c));
    return d;
}
__device__ __forceinline__ ull mul2(ull a, ull b) {
    ull d;
    asm("mul.rn.f32x2 %0, %1, %2;" : "=l"(d) : "l"(a), "l"(b));
    return d;
}
__device__ __forceinline__ ull add2(ull a, ull b) {
    ull d;
    asm("add.rn.f32x2 %0, %1, %2;" : "=l"(d) : "l"(a), "l"(b));
    return d;
}
__device__ __forceinline__ float ex2f(float x) {
    float r;
    asm("ex2.approx.f32 %0, %1;" : "=f"(r) : "f"(x));
    return r;
}

// ---------------------------------------------------------------------------
// Kernel 1: GroupNorm (8 groups of 32 channels x 1024). One block per (n,g).
// ---------------------------------------------------------------------------
__global__ void gn_kernel(const float* __restrict__ x,
                          const float* __restrict__ gn_w,
                          const float* __restrict__ gn_b) {
    int n = blockIdx.x >> 3;
    int g = blockIdx.x & 7;
    const float4* xp = (const float4*)(x + (size_t)(n * C + g * CPG) * HW);
    float4* op = (float4*)(g_xn + (size_t)(n * C + g * CPG) * HW);

    float s = 0.f, ss = 0.f;
#pragma unroll 4
    for (int i = threadIdx.x; i < 8192; i += 256) {
        float4 v = xp[i];
        s  += v.x + v.y + v.z + v.w;
        ss += v.x * v.x + v.y * v.y + v.z * v.z + v.w * v.w;
    }
#pragma unroll
    for (int off = 16; off; off >>= 1) {
        s  += __shfl_down_sync(0xffffffffu, s, off);
        ss += __shfl_down_sync(0xffffffffu, ss, off);
    }
    __shared__ float rs[8], rss[8];
    __shared__ float s_mu, s_rinv;
    int warp = threadIdx.x >> 5, lane = threadIdx.x & 31;
    if (lane == 0) { rs[warp] = s; rss[warp] = ss; }
    __syncthreads();
    if (threadIdx.x == 0) {
        float ts = 0.f, tss = 0.f;
#pragma unroll
        for (int w = 0; w < 8; ++w) { ts += rs[w]; tss += rss[w]; }
        float mu  = ts * (1.f / 32768.f);
        float var = tss * (1.f / 32768.f) - mu * mu;
        s_mu = mu;
        s_rinv = rsqrtf(var + 1e-5f);
    }
    __syncthreads();
    float mu = s_mu, rinv = s_rinv;
#pragma unroll 4
    for (int i = threadIdx.x; i < 8192; i += 256) {
        int cl = i >> 8;  // 256 float4 per channel
        float w = __ldg(&gn_w[g * CPG + cl]) * rinv;
        float b = __ldg(&gn_b[g * CPG + cl]) - mu * w;
        float4 v = xp[i];
        float4 o;
        o.x = v.x * w + b; o.y = v.y * w + b;
        o.z = v.z * w + b; o.w = v.w * w + b;
        op[i] = o;
    }
}

// ---------------------------------------------------------------------------
// Kernel 2/4: batched GEMM  Out[n][o][t] = sum_c W[o][c]*In[n][c][t] + bias[o]
// (+ optional residual X). K = 256. Tile 64x64, BK=32, 4x4/thread.
// Double-buffered register-staged prefetch + f32x2 MACs (R11 version,
// measured equal to scalar, fewer regs).
// ---------------------------------------------------------------------------
template <bool RESIDUAL>
__global__ void gemm_kernel(const float* __restrict__ W,
                            const float* __restrict__ bias,
                            const float* __restrict__ In,
                            const float* __restrict__ X,
                            float* __restrict__ Out, int M) {
    __shared__ __align__(16) float As[2][32][68];  // [buf][c][o]
    __shared__ __align__(16) float Bs[2][32][64];  // [buf][c][t]

    int n  = blockIdx.z;
    int mo = blockIdx.y * 64;
    int to = blockIdx.x * 64;
    int tid = threadIdx.x;
    int tm = tid >> 4, tn = tid & 15;

    const float* Wp = W + (size_t)mo * C;
    const float* Ip = In + (size_t)n * (C * HW) + to;

    int ao0 = tid >> 3,          ac0 = (tid & 7) * 4;
    int ao1 = (tid + 256) >> 3,  ac1 = (tid & 7) * 4;
    int bc0 = tid >> 4,  bt0 = (tid & 15) * 4;
    int bc1 = bc0 + 16;

    const float* ApA = Wp + ao0 * C + ac0;
    const float* ApB = Wp + ao1 * C + ac1;
    const float* BpA = Ip + bc0 * HW + bt0;
    const float* BpB = Ip + bc1 * HW + bt0;

    float4 a0r = *(const float4*)(ApA);
    float4 a1r = *(const float4*)(ApB);
    float4 b0r = *(const float4*)(BpA);
    float4 b1r = *(const float4*)(BpB);

    ull acc2[2][4];  // packed over (m, m+1) pairs
#pragma unroll
    for (int i = 0; i < 2; ++i)
#pragma unroll
        for (int j = 0; j < 4; ++j) acc2[i][j] = 0ull;

    As[0][ac0 + 0][ao0] = a0r.x; As[0][ac0 + 1][ao0] = a0r.y;
    As[0][ac0 + 2][ao0] = a0r.z; As[0][ac0 + 3][ao0] = a0r.w;
    As[0][ac1 + 0][ao1] = a1r.x; As[0][ac1 + 1][ao1] = a1r.y;
    As[0][ac1 + 2][ao1] = a1r.z; As[0][ac1 + 3][ao1] = a1r.w;
    *(float4*)&Bs[0][bc0][bt0] = b0r;
    *(float4*)&Bs[0][bc1][bt0] = b1r;
    __syncthreads();

    int buf = 0;
#pragma unroll 1
    for (int k0 = 32; ; k0 += 32) {
        bool more = (k0 < C);
        if (more) {
            a0r = *(const float4*)(ApA + k0);
            a1r = *(const float4*)(ApB + k0);
            b0r = *(const float4*)(BpA + k0 * HW);
            b1r = *(const float4*)(BpB + k0 * HW);
        }
#pragma unroll
        for (int k = 0; k < 32; ++k) {
            ulonglong2 a = *(const ulonglong2*)&As[buf][k][tm * 4];
            float4 b = *(const float4*)&Bs[buf][k][tn * 4];
            ull b0 = pack2(b.x, b.x), b1 = pack2(b.y, b.y);
            ull b2 = pack2(b.z, b.z), b3 = pack2(b.w, b.w);
            acc2[0][0] = fma2(a.x, b0, acc2[0][0]);
            acc2[0][1] = fma2(a.x, b1, acc2[0][1]);
            acc2[0][2] = fma2(a.x, b2, acc2[0][2]);
            acc2[0][3] = fma2(a.x, b3, acc2[0][3]);
            acc2[1][0] = fma2(a.y, b0, acc2[1][0]);
            acc2[1][1] = fma2(a.y, b1, acc2[1][1]);
            acc2[1][2] = fma2(a.y, b2, acc2[1][2]);
            acc2[1][3] = fma2(a.y, b3, acc2[1][3]);
        }
        if (!more) break;
        __syncthreads();
        int nb = buf ^ 1;
        As[nb][ac0 + 0][ao0] = a0r.x; As[nb][ac0 + 1][ao0] = a0r.y;
        As[nb][ac0 + 2][ao0] = a0r.z; As[nb][ac0 + 3][ao0] = a0r.w;
        As[nb][ac1 + 0][ao1] = a1r.x; As[nb][ac1 + 1][ao1] = a1r.y;
        As[nb][ac1 + 2][ao1] = a1r.z; As[nb][ac1 + 3][ao1] = a1r.w;
        *(float4*)&Bs[nb][bc0][bt0] = b0r;
        *(float4*)&Bs[nb][bc1][bt0] = b1r;
        buf = nb;
        __syncthreads();
    }

#pragma unroll
    for (int mp = 0; mp < 2; ++mp) {
        float lo[4], hi[4];
#pragma unroll
        for (int j = 0; j < 4; ++j) unpack2(acc2[mp][j], lo[j], hi[j]);
#pragma unroll
        for (int half = 0; half < 2; ++half) {
            float* rr = half ? hi : lo;
            int o = mo + tm * 4 + mp * 2 + half;
            float bi = __ldg(&bias[o]);
            size_t off = (size_t)(n * M + o) * HW + to + tn * 4;
            float4 r;
            r.x = rr[0] + bi; r.y = rr[1] + bi;
            r.z = rr[2] + bi; r.w = rr[3] + bi;
            if (RESIDUAL) {
                float4 xv = *(const float4*)(X + off);
                r.x += xv.x; r.y += xv.y; r.z += xv.z; r.w += xv.w;
            }
            *(float4*)(Out + off) = r;
        }
    }
}

// ---------------------------------------------------------------------------
// Kernel 3: attention, t-parity packing (R11 layout) + latency fixes:
// unroll 4 and tree-form QK dot (two 4-deep chains + add2: depth 8 -> 5,
// 4 independent chains per thread). Block = (h, n, s-half); 256 threads x
// 2 s-rows. SMEM 64 KB: K,V as natural even/odd t-pairs (no duplication).
// No max subtraction (scores ~N(0,1)); exp2 via pre-scaled q.
// ---------------------------------------------------------------------------
__global__ void __launch_bounds__(256, 2) attn_kernel() {
    extern __shared__ float sm[];
    float* kS = sm;              // [tp][16]
    float* vS = sm + TP * 16;

    int h = blockIdx.x, n = blockIdx.y, sh = blockIdx.z;
    const float* base = g_qkv + (size_t)n * (THREE_C * HW);
    const float* qg = base + (h * D) * HW;
    const float* kg = base + (C + h * D) * HW;
    const float* vg = base + (2 * C + h * D) * HW;

    // Fill: float2 gmem loads are exactly the (even,odd) pairs we need.
    for (int tp = threadIdx.x; tp < TP; tp += 256) {
        float* kd = kS + tp * 16;
        float* vd = vS + tp * 16;
#pragma unroll
        for (int d = 0; d < 8; ++d) {
            *(float2*)(kd + 2 * d) = *(const float2*)(kg + d * HW + 2 * tp);
            *(float2*)(vd + 2 * d) = *(const float2*)(vg + d * HW + 2 * tp);
        }
    }
    __syncthreads();

    // q pre-scaled by (1/sqrt(8)) * log2(e); duplicated into both lanes.
    const float qscale = 0.35355339059327373f * 1.4426950408889634f;
    int s0 = sh * 512 + threadIdx.x;   // row A
    int s1 = s0 + 256;                 // row B
    ull qa[8], qb[8];
#pragma unroll
    for (int d = 0; d < 8; ++d) {
        const float* qd = qg + d * HW;
        float q0 = qd[s0] * qscale, q1 = qd[s1] * qscale;
        qa[d] = pack2(q0, q0);
        qb[d] = pack2(q1, q1);
    }

    ull acca[8], accb[8];
#pragma unroll
    for (int d = 0; d < 8; ++d) { acca[d] = 0ull; accb[d] = 0ull; }
    ull la = 0ull, lb = 0ull;

#pragma unroll 4
    for (int tp = 0; tp < TP; ++tp) {
        const ulonglong2* kp = (const ulonglong2*)(kS + tp * 16);
        ulonglong2 k01 = kp[0], k23 = kp[1], k45 = kp[2], k67 = kp[3];
        // Tree QK: two 4-deep chains per stream, then one add2.
        ull ua0 = fma2(qa[3], k23.y,
                  fma2(qa[2], k23.x,
                  fma2(qa[1], k01.y, mul2(qa[0], k01.x))));
        ull ua1 = fma2(qa[7], k67.y,
                  fma2(qa[6], k67.x,
                  fma2(qa[5], k45.y, mul2(qa[4], k45.x))));
        ull ub0 = fma2(qb[3], k23.y,
                  fma2(qb[2], k23.x,
                  fma2(qb[1], k01.y, mul2(qb[0], k01.x))));
        ull ub1 = fma2(qb[7], k67.y,
                  fma2(qb[6], k67.x,
                  fma2(qb[5], k45.y, mul2(qb[4], k45.x))));
        ull sa = add2(ua0, ua1);
        ull sb = add2(ub0, ub1);

        float f0, f1, f2, f3;
        unpack2(sa, f0, f1);
        unpack2(sb, f2, f3);
        ull ea = pack2(ex2f(f0), ex2f(f1));   // weights for (t_even, t_odd)
        ull eb = pack2(ex2f(f2), ex2f(f3));
        la = add2(la, ea);
        lb = add2(lb, eb);

        const ulonglong2* vp = (const ulonglong2*)(vS + tp * 16);
        ulonglong2 v01 = vp[0], v23 = vp[1], v45 = vp[2], v67 = vp[3];
        acca[0] = fma2(ea, v01.x, acca[0]); accb[0] = fma2(eb, v01.x, accb[0]);
        acca[1] = fma2(ea, v01.y, acca[1]); accb[1] = fma2(eb, v01.y, accb[1]);
        acca[2] = fma2(ea, v23.x, acca[2]); accb[2] = fma2(eb, v23.x, accb[2]);
        acca[3] = fma2(ea, v23.y, acca[3]); accb[3] = fma2(eb, v23.y, accb[3]);
        acca[4] = fma2(ea, v45.x, acca[4]); accb[4] = fma2(eb, v45.x, accb[4]);
        acca[5] = fma2(ea, v45.y, acca[5]); accb[5] = fma2(eb, v45.y, accb[5]);
        acca[6] = fma2(ea, v67.x, acca[6]); accb[6] = fma2(eb, v67.x, accb[6]);
        acca[7] = fma2(ea, v67.y, acca[7]); accb[7] = fma2(eb, v67.y, accb[7]);
    }

    // Horizontal reduce the t-parity lanes, normalize, store.
    float la0, la1, lb0, lb1;
    unpack2(la, la0, la1);
    unpack2(lb, lb0, lb1);
    float invA = 1.f / (la0 + la1);
    float invB = 1.f / (lb0 + lb1);
    float* ypA = g_y + (size_t)(n * C + h * D) * HW + s0;
    float* ypB = g_y + (size_t)(n * C + h * D) * HW + s1;
#pragma unroll
    for (int d = 0; d < 8; ++d) {
        float a0, a1, b0, b1;
        unpack2(acca[d], a0, a1);
        unpack2(accb[d], b0, b1);
        ypA[d * HW] = (a0 + a1) * invA;
        ypB[d * HW] = (b0 + b1) * invB;
    }
}

// ---------------------------------------------------------------------------
extern "C" void kernel_launch(void* const* d_in, const int* in_sizes, int n_in,
                              void* d_out, int out_size) {
    const float* x     = (const float*)d_in[0];
    const float* gn_w  = (const float*)d_in[1];
    const float* gn_b  = (const float*)d_in[2];
    const float* qkv_w = (const float*)d_in[3];
    const float* qkv_b = (const float*)d_in[4];
    const float* out_w = (const float*)d_in[5];
    const float* out_b = (const float*)d_in[6];
    float* out = (float*)d_out;

    float *p_xn, *p_qkv, *p_y;
    cudaGetSymbolAddress((void**)&p_xn, g_xn);
    cudaGetSymbolAddress((void**)&p_qkv, g_qkv);
    cudaGetSymbolAddress((void**)&p_y, g_y);

    // 1. GroupNorm -> g_xn
    gn_kernel<<<64, 256>>>(x, gn_w, gn_b);

    // 2. QKV GEMM: g_qkv[n][768][1024]
    gemm_kernel<false><<<dim3(16, 12, 8), 256>>>(
        qkv_w, qkv_b, p_xn, nullptr, p_qkv, THREE_C);

    // 3. Attention -> g_y  (64 KB dynamic SMEM: full K+V as t-parity pairs)
    const int attn_smem = 2 * TP * 16 * sizeof(float);  // 65536
    cudaFuncSetAttribute(attn_kernel,
                         cudaFuncAttributeMaxDynamicSharedMemorySize, attn_smem);
    attn_kernel<<<dim3(NH, N_BATCH, 2), 256, attn_smem>>>();

    // 4. Output projection + residual -> d_out
    gemm_kernel<true><<<dim3(16, 4, 8), 256>>>(
        out_w, out_b, p_y, x, out, C);
}